// round 8
// baseline (speedup 1.0000x reference)
#include <cuda_runtime.h>
#include <math_constants.h>

#define N 384
#define D 128
#define MARGIN 0.2f
#define RHO 10.0f
#define NTILE 12              // 384/32
#define NBLK (NTILE * NTILE)  // 144 blocks, single wave (<=148 SMs)
#define GA 3
#define NANCBLK (N / GA)      // 128 blocks do phase 2
#define NT 256
#define NWARP (NT / 32)       // 8

__device__ float  g_dist[N * N];
__device__ double g_num;
__device__ int    g_den;
__device__ int    g_bar;      // phase-1 grid barrier counter
__device__ int    g_count;    // completion counter; last block resets all

struct P1 {
    float As[32][D];
    float Bs[D][33];
    float sqA[32], sqB[32];
};
struct P2 {
    float  drow[GA][N];
    float  dval[GA][N];
    int    cls[N];
    short  poslist[GA][N];
    int    npos[GA];
    double warpsum[NWARP];
};

__global__ void __launch_bounds__(NT, 1)
facenet_kernel(const int* __restrict__ classes,
               const float* __restrict__ emb,
               float* __restrict__ out) {
    __shared__ __align__(16) char smraw[sizeof(P1) > sizeof(P2) ? sizeof(P1) : sizeof(P2)];
    const int tid = threadIdx.x;
    const int b   = blockIdx.x;

    // ================= Phase 1: 32x32 distance tile =================
    {
        P1* s = reinterpret_cast<P1*>(smraw);
        const int bi = (b / NTILE) * 32;
        const int bj = (b % NTILE) * 32;

        for (int idx = tid; idx < 32 * D; idx += NT) {
            int r = idx >> 7;
            int c = idx & (D - 1);
            s->As[r][c] = emb[(bi + r) * D + c];
            s->Bs[c][r] = emb[(bj + r) * D + c];
        }
        __syncthreads();

        if (tid < 32) {
            float v = 0.f;
#pragma unroll
            for (int d = 0; d < D; d++) v = fmaf(s->As[tid][d], s->As[tid][d], v);
            s->sqA[tid] = v;
        } else if (tid < 64) {
            const int r = tid - 32;
            float v = 0.f;
#pragma unroll
            for (int d = 0; d < D; d++) v = fmaf(s->Bs[d][r], s->Bs[d][r], v);
            s->sqB[r] = v;
        }
        __syncthreads();

        const int c  = tid & 31;
        const int r0 = tid >> 5;
        float acc[4] = {0.f, 0.f, 0.f, 0.f};
        for (int d = 0; d < D; d++) {
            float bb = s->Bs[d][c];
#pragma unroll
            for (int q = 0; q < 4; q++)
                acc[q] = fmaf(s->As[r0 + 8 * q][d], bb, acc[q]);
        }
#pragma unroll
        for (int q = 0; q < 4; q++) {
            const int r = r0 + 8 * q;
            float dist = s->sqA[r] + s->sqB[c] - 2.0f * acc[q];
            g_dist[(bi + r) * N + (bj + c)] = fmaxf(dist, 0.0f);
        }
    }

    // ================= Grid barrier (144 co-resident blocks) =========
    __threadfence();
    __syncthreads();
    if (tid == 0) {
        atomicAdd(&g_bar, 1);
        while (*(volatile int*)&g_bar < NBLK) __nanosleep(32);
    }
    __syncthreads();
    __threadfence();   // acquire: see all blocks' g_dist stores

    // ================= Phase 2: triplet scan (blocks 0..127) ========
    double blocknum = 0.0;
    int    blockden = 0;

    if (b < NANCBLK) {
        P2* s = reinterpret_cast<P2*>(smraw);
        const int base = b * GA;

        for (int k = tid; k < N; k += NT) s->cls[k] = classes[k];
        if (tid < GA) s->npos[tid] = 0;
        __syncthreads();

        // load 3 dist rows (float4), mask, build positive lists
#pragma unroll
        for (int g = 0; g < GA; g++) {
            const int a  = base + g;
            const int ca = s->cls[a];
            const float4* row = reinterpret_cast<const float4*>(g_dist + a * N);
            for (int q = tid; q < N / 4; q += NT) {
                float4 v = row[q];
                const int k0 = q * 4;
#pragma unroll
                for (int e = 0; e < 4; e++) {
                    const int k = k0 + e;
                    float dist = (e == 0) ? v.x : (e == 1) ? v.y : (e == 2) ? v.z : v.w;
                    s->drow[g][k] = dist;
                    bool same = (s->cls[k] == ca);
                    s->dval[g][k] = same ? CUDART_INF_F : dist;
                    if (same && k != a) {
                        int p = atomicAdd(&s->npos[g], 1);
                        s->poslist[g][p] = (short)k;
                    }
                }
            }
        }
        __syncthreads();

        const int np0 = s->npos[0], np1 = s->npos[1], np2 = s->npos[2];
        const int ntot = np0 + np1 + np2;
        blockden = ntot;

        const int warp = tid >> 5;
        const int lane = tid & 31;
        double wsum = 0.0;

        for (int p = warp; p < ntot; p += NWARP) {
            int g, l;
            if (p < np0)            { g = 0; l = p; }
            else if (p < np0 + np1) { g = 1; l = p - np0; }
            else                    { g = 2; l = p - np0 - np1; }

            const float t = s->drow[g][s->poslist[g][l]];  // d(i,j)
            const float* dv = s->dval[g];

            float minw = CUDART_INF_F;    // min x in [0, MARGIN)
            float maxn = -CUDART_INF_F;   // max x < 0
#pragma unroll
            for (int kk = 0; kk < N / 32; kk++) {
                float x = dv[kk * 32 + lane] - t;
                minw = fminf(minw, (x >= 0.0f && x < MARGIN) ? x : CUDART_INF_F);
                maxn = fmaxf(maxn, (x < 0.0f) ? x : -CUDART_INF_F);
            }
#pragma unroll
            for (int off = 16; off; off >>= 1) {
                minw = fminf(minw, __shfl_xor_sync(0xffffffffu, minw, off));
                maxn = fmaxf(maxn, __shfl_xor_sync(0xffffffffu, maxn, off));
            }
            float semimax = (minw < CUDART_INF_F) ? (MARGIN - minw) : 0.0f;
            float minhard = MARGIN - maxn;
            float pph = (minhard < RHO) ? minhard : 0.0f;
            wsum += (double)((semimax > 0.0f) ? semimax : pph);
        }

        if (lane == 0) s->warpsum[warp] = wsum;
        __syncthreads();
        if (tid == 0) {
            double t2 = 0.0;
#pragma unroll
            for (int w = 0; w < NWARP; w++) t2 += s->warpsum[w];
            blocknum = t2;
        }
    }

    // ================= Tail: accumulate, finalize, reset =============
    if (tid == 0) {
        if (blocknum != 0.0) atomicAdd(&g_num, blocknum);
        if (blockden != 0)   atomicAdd(&g_den, blockden);
        __threadfence();
        int c = atomicAdd(&g_count, 1);
        if (c == NBLK - 1) {                 // last of all 144 blocks
            double num = *(volatile double*)&g_num;
            int    den = *(volatile int*)&g_den;
            double r = (den > 0) ? (num / fmax((double)den, 1.0)) : 0.0;
            out[0] = (float)r;
            g_num = 0.0;
            g_den = 0;
            g_bar = 0;
            __threadfence();
            g_count = 0;
        }
    }
}

extern "C" void kernel_launch(void* const* d_in, const int* in_sizes, int n_in,
                              void* d_out, int out_size) {
    const int*   classes = (const int*)d_in[0];
    const float* emb     = (const float*)d_in[1];
    facenet_kernel<<<NBLK, NT>>>(classes, emb, (float*)d_out);
}

// round 9
// speedup vs baseline: 1.1193x; 1.1193x over previous
#include <cuda_runtime.h>
#include <math_constants.h>

#define N 384
#define D 128
#define MARGIN 0.2f
#define RHO 10.0f
#define GA 3
#define NBLK_T (N / GA)       // 128 triplet blocks = one wave
#define NWARP 8               // 256 threads

__device__ float  g_dist[N * N];
__device__ double g_num;
__device__ int    g_den;
__device__ int    g_count;    // zero-init; last block resets each replay

// ---------------------------------------------------------------------------
// Kernel A: pairwise squared distances, tiled 32x32 Gram, norms from smem.
// grid (12,12) = 144 blocks (one wave), 256 threads.  [unchanged from R3]
// ---------------------------------------------------------------------------
__global__ void __launch_bounds__(256)
dist_kernel(const float* __restrict__ emb) {
    __shared__ float As[32][D];
    __shared__ float Bs[D][33];
    __shared__ float sqA[32], sqB[32];

    const int bi = blockIdx.y * 32;
    const int bj = blockIdx.x * 32;
    const int tid = threadIdx.x;

    for (int idx = tid; idx < 32 * D; idx += 256) {
        int r = idx >> 7;
        int c = idx & (D - 1);
        As[r][c] = emb[(bi + r) * D + c];
        Bs[c][r] = emb[(bj + r) * D + c];
    }
    __syncthreads();

    if (tid < 32) {
        float s = 0.f;
#pragma unroll
        for (int d = 0; d < D; d++) s = fmaf(As[tid][d], As[tid][d], s);
        sqA[tid] = s;
    } else if (tid < 64) {
        const int r = tid - 32;
        float s = 0.f;
#pragma unroll
        for (int d = 0; d < D; d++) s = fmaf(Bs[d][r], Bs[d][r], s);
        sqB[r] = s;
    }
    __syncthreads();

    const int c  = tid & 31;
    const int r0 = tid >> 5;
    float acc[4] = {0.f, 0.f, 0.f, 0.f};
    for (int d = 0; d < D; d++) {
        float b = Bs[d][c];
#pragma unroll
        for (int q = 0; q < 4; q++)
            acc[q] = fmaf(As[r0 + 8 * q][d], b, acc[q]);
    }
#pragma unroll
    for (int q = 0; q < 4; q++) {
        const int r = r0 + 8 * q;
        float dist = sqA[r] + sqB[c] - 2.0f * acc[q];
        g_dist[(bi + r) * N + (bj + c)] = fmaxf(dist, 0.0f);
    }
}

// ---------------------------------------------------------------------------
// Kernel B: triplet reduction, 128 blocks x 3 anchors = ONE wave, + finalize.
// ---------------------------------------------------------------------------
__global__ void __launch_bounds__(256)
triplet_kernel(const int* __restrict__ classes, float* __restrict__ out) {
    __shared__ float  drow[GA][N];
    __shared__ float  dval[GA][N];
    __shared__ int    cls[N];
    __shared__ short  poslist[GA][N];
    __shared__ int    npos[GA];
    __shared__ double warpsum[NWARP];
    __shared__ bool   islast;

    const int tid  = threadIdx.x;      // 256 threads, 8 warps
    const int base = blockIdx.x * GA;

    for (int k = tid; k < N; k += 256) cls[k] = classes[k];
    if (tid < GA) npos[tid] = 0;
    __syncthreads();

    // load 3 dist rows (float4), mask, build positive lists
#pragma unroll
    for (int g = 0; g < GA; g++) {
        const int a  = base + g;
        const int ca = cls[a];
        const float4* row = reinterpret_cast<const float4*>(g_dist + a * N);
        for (int q = tid; q < N / 4; q += 256) {
            float4 v = row[q];
            const int k0 = q * 4;
#pragma unroll
            for (int e = 0; e < 4; e++) {
                const int k = k0 + e;
                float dist = (e == 0) ? v.x : (e == 1) ? v.y : (e == 2) ? v.z : v.w;
                drow[g][k] = dist;
                bool same = (cls[k] == ca);
                dval[g][k] = same ? CUDART_INF_F : dist;
                if (same && k != a) {
                    int p = atomicAdd(&npos[g], 1);
                    poslist[g][p] = (short)k;
                }
            }
        }
    }
    __syncthreads();

    const int np0 = npos[0], np1 = npos[1], np2 = npos[2];
    const int ntot = np0 + np1 + np2;
    if (tid == 0 && ntot > 0) atomicAdd(&g_den, ntot);

    const int warp = tid >> 5;
    const int lane = tid & 31;
    double wsum = 0.0;

    for (int p = warp; p < ntot; p += NWARP) {
        int g, l;
        if (p < np0)            { g = 0; l = p; }
        else if (p < np0 + np1) { g = 1; l = p - np0; }
        else                    { g = 2; l = p - np0 - np1; }

        const float t = drow[g][poslist[g][l]];   // d(i, j)
        const float* dv = dval[g];

        float minw = CUDART_INF_F;    // min x in [0, MARGIN)
        float maxn = -CUDART_INF_F;   // max x < 0
#pragma unroll
        for (int kk = 0; kk < N / 32; kk++) {
            float x = dv[kk * 32 + lane] - t;     // d(i,k) - d(i,j)
            minw = fminf(minw, (x >= 0.0f && x < MARGIN) ? x : CUDART_INF_F);
            maxn = fmaxf(maxn, (x < 0.0f) ? x : -CUDART_INF_F);
        }
#pragma unroll
        for (int off = 16; off; off >>= 1) {
            minw = fminf(minw, __shfl_xor_sync(0xffffffffu, minw, off));
            maxn = fmaxf(maxn, __shfl_xor_sync(0xffffffffu, maxn, off));
        }
        float semimax = (minw < CUDART_INF_F) ? (MARGIN - minw) : 0.0f;
        float minhard = MARGIN - maxn;            // +INF if no hard k
        float pph = (minhard < RHO) ? minhard : 0.0f;
        wsum += (double)((semimax > 0.0f) ? semimax : pph);
    }

    if (lane == 0) warpsum[warp] = wsum;
    __syncthreads();

    if (tid == 0) {
        double s = 0.0;
#pragma unroll
        for (int w = 0; w < NWARP; w++) s += warpsum[w];
        if (s != 0.0) atomicAdd(&g_num, s);
        __threadfence();
        int c = atomicAdd(&g_count, 1);
        islast = (c == NBLK_T - 1);
    }
    __syncthreads();

    if (islast && tid == 0) {
        double num = *(volatile double*)&g_num;   // ordered by fence+counter
        int    den = *(volatile int*)&g_den;
        double r = (den > 0) ? (num / fmax((double)den, 1.0)) : 0.0;
        out[0] = (float)r;
        g_num = 0.0;
        g_den = 0;
        __threadfence();
        g_count = 0;
    }
}

// ---------------------------------------------------------------------------
extern "C" void kernel_launch(void* const* d_in, const int* in_sizes, int n_in,
                              void* d_out, int out_size) {
    const int*   classes = (const int*)d_in[0];
    const float* emb     = (const float*)d_in[1];

    dim3 grid(N / 32, N / 32);        // 144 blocks, one wave
    dist_kernel<<<grid, 256>>>(emb);
    triplet_kernel<<<NBLK_T, 256>>>(classes, (float*)d_out);
}